// round 8
// baseline (speedup 1.0000x reference)
#include <cuda_runtime.h>
#include <cuda_bf16.h>

// Lp_Conv2D_BT: out[b,o,i,j] = max_{k<4} | w[o,k] - x_pad[b, c_k, i+di_k-1, j+dj_k-1] | + bias[o]
// edge padding (clamp), stride 1.
// x:(32,64,64,64) f32; weights:(128,4) f32; bias:(128,1,1) f32; conn_idx:(128,4) i32.
// out:(32,128,64,64) f32.

namespace {
constexpr int HW   = 64;
constexpr int CIN  = 64;
constexpr int COUT = 128;
constexpr int CONN = 4;
}

__global__ __launch_bounds__(256) void lp_conv_bt_kernel(
    const float* __restrict__ x,
    const float* __restrict__ weights,
    const float* __restrict__ bias,
    const int*   __restrict__ conn_idx,
    float*       __restrict__ out)
{
    const int blk = blockIdx.x;          // blk = b*COUT + o
    const int o   = blk & (COUT - 1);
    const int b   = blk >> 7;
    const int t   = threadIdx.x;

    const int lane16 = t & 15;
    const int r0     = t >> 4;           // 0..15
    const bool laneLo = (lane16 == 0);
    const bool laneHi = (lane16 == 15);

    const float* xb = x + (size_t)b * CIN * (HW * HW);

    // Per-output-channel connection parameters (uniform across the block).
    const float* bp[CONN];
    int a0[CONN], a3[CONN], dc[CONN];
    float w[CONN];
#pragma unroll
    for (int k = 0; k < CONN; ++k) {
        const int idx = __ldg(conn_idx + o * CONN + k);   // [0, 576)
        const int c   = idx / 9;
        const int rem = idx - c * 9;
        const int di  = rem / 3;
        const int drk = di - 1;                            // {-1,0,1}
        dc[k] = (rem - di * 3) - 1;                        // {-1,0,1}
        w[k]  = __ldg(weights + o * CONN + k);
        bp[k] = xb + c * (HW * HW) + (r0 + drk) * HW + lane16 * 4;
        a0[k] = ((r0 + drk) < 0) ? HW : 0;                 // only r0==0, dr==-1
        a3[k] = ((r0 + 48 + drk) > HW - 1) ? -HW : 0;      // only r0==15, dr==+1
    }
    const float bs = __ldg(bias + o);

    // 16 max-accumulators: m[rb][j], all >= 0.
    float m[4][4];
#pragma unroll
    for (int rb = 0; rb < 4; ++rb)
#pragma unroll
        for (int j = 0; j < 4; ++j) m[rb][j] = 0.f;

    // k outer: 4 loads (MLP=4), ONE uniform dc branch, then 4 straight-line
    // row-block accumulates inside the taken arm.
#pragma unroll
    for (int k = 0; k < CONN; ++k) {
        float4 v[4];
        v[0] = __ldg(reinterpret_cast<const float4*>(bp[k] + a0[k]));
        v[1] = __ldg(reinterpret_cast<const float4*>(bp[k] + 16 * HW));
        v[2] = __ldg(reinterpret_cast<const float4*>(bp[k] + 32 * HW));
        v[3] = __ldg(reinterpret_cast<const float4*>(bp[k] + 48 * HW + a3[k]));
        const float wk = w[k];

        if (dc[k] == 0) {
#pragma unroll
            for (int rb = 0; rb < 4; ++rb) {
                m[rb][0] = fmaxf(m[rb][0], fabsf(wk - v[rb].x));
                m[rb][1] = fmaxf(m[rb][1], fabsf(wk - v[rb].y));
                m[rb][2] = fmaxf(m[rb][2], fabsf(wk - v[rb].z));
                m[rb][3] = fmaxf(m[rb][3], fabsf(wk - v[rb].w));
            }
        } else if (dc[k] > 0) {
#pragma unroll
            for (int rb = 0; rb < 4; ++rb) {
                // cols j0+1..j0+4 ; j0+4 = next lane's v.x (col 64 -> clamp 63 = v.w)
                float e = __shfl_down_sync(0xffffffffu, v[rb].x, 1, 16);
                if (laneHi) e = v[rb].w;
                m[rb][0] = fmaxf(m[rb][0], fabsf(wk - v[rb].y));
                m[rb][1] = fmaxf(m[rb][1], fabsf(wk - v[rb].z));
                m[rb][2] = fmaxf(m[rb][2], fabsf(wk - v[rb].w));
                m[rb][3] = fmaxf(m[rb][3], fabsf(wk - e));
            }
        } else {
#pragma unroll
            for (int rb = 0; rb < 4; ++rb) {
                // cols j0-1..j0+2 ; j0-1 = prev lane's v.w (col -1 -> clamp 0 = v.x)
                float e = __shfl_up_sync(0xffffffffu, v[rb].w, 1, 16);
                if (laneLo) e = v[rb].x;
                m[rb][0] = fmaxf(m[rb][0], fabsf(wk - e));
                m[rb][1] = fmaxf(m[rb][1], fabsf(wk - v[rb].x));
                m[rb][2] = fmaxf(m[rb][2], fabsf(wk - v[rb].y));
                m[rb][3] = fmaxf(m[rb][3], fabsf(wk - v[rb].z));
            }
        }
    }

    // Epilogue: bias + streaming float4 stores (contiguous per lane).
    float4* po = reinterpret_cast<float4*>(out + (size_t)blk * (HW * HW)) + r0 * 16 + lane16;
#pragma unroll
    for (int rb = 0; rb < 4; ++rb) {
        __stcs(po + rb * 16 * 16,
               make_float4(m[rb][0] + bs, m[rb][1] + bs, m[rb][2] + bs, m[rb][3] + bs));
    }
}

extern "C" void kernel_launch(void* const* d_in, const int* in_sizes, int n_in,
                              void* d_out, int out_size) {
    const float* x       = (const float*)d_in[0];
    const float* weights = (const float*)d_in[1];
    const float* bias    = (const float*)d_in[2];
    const int*   conn    = (const int*)d_in[3];
    float*       out     = (float*)d_out;

    const int B = in_sizes[0] / (CIN * HW * HW);   // 32
    lp_conv_bt_kernel<<<B * COUT, 256>>>(x, weights, bias, conn, out);
}